// round 15
// baseline (speedup 1.0000x reference)
#include <cuda_runtime.h>

#define L 8
#define A 4
#define D 256
#define SEQ 16384
#define SB 16
#define HALF 8
#define NBATCH (SEQ / SB)   // 1024
#define NSLOT 256           // ring steps = 16 batches of elasticity

// ---------------- device scratch ----------------
__device__ float g_P[L * A * D];
__device__ float g_S[L * A];
__device__ unsigned char g_seq8[SEQ];
__device__ float2 g_ring[L][NSLOT][D];          // 4 MB level-state ring
__device__ float2 g_scr[L][8][4][HALF][32];     // shipped conv results (quad buf)
__device__ int g_prod[L];                       // +8 per published batch
__device__ int g_cons[L];                       // +16 per staged batch
__device__ int g_scrf[L][8];                    // shipper -> updater
__device__ int g_scrc[L][8];                    // updater -> shipper

__device__ __forceinline__ int vload(const int* p)  { return *(volatile const int*)p; }

// ---------------- kernel 0: pack sequence (verbatim) ----------------
__global__ void pack_seq_k(const int* __restrict__ seq) {
    int i = blockIdx.x * blockDim.x + threadIdx.x;
    if (i < SEQ) g_seq8[i] = (unsigned char)(seq[i] & 3);
}

// ---------------- kernel 0b: reset counters + zero step(-1) ring slot ----------------
__global__ void init_flags_k() {
    int t = blockIdx.x * blockDim.x + threadIdx.x;
    if (t < L) { g_prod[t] = 0; g_cons[t] = 0; }
    if (t < L * 8) { ((int*)g_scrf)[t] = 0; ((int*)g_scrc)[t] = 0; }
    for (int q = t; q < L * D; q += gridDim.x * blockDim.x) {
        int lv = q >> 8, j = q & 255;
        g_ring[lv][NSLOT - 1][j] = make_float2(0.f, 0.f);
    }
}

// ---------------- kernel 1: literal softmax + sigmoid (verbatim) ----------------
__global__ void precompute_lit_k(const float* __restrict__ hash_emb,
                                 const float* __restrict__ sign_logits) {
    int b = blockIdx.x;
    int t = threadIdx.x;
    __shared__ float sh[D];

    float x = hash_emb[b * D + t];
    sh[t] = x;
    __syncthreads();
    for (int o = 128; o > 0; o >>= 1) {
        if (t < o) sh[t] = fmaxf(sh[t], sh[t + o]);
        __syncthreads();
    }
    float mx = sh[0];
    __syncthreads();
    float e = expf(x - mx);
    sh[t] = e;
    __syncthreads();
    for (int o = 128; o > 0; o >>= 1) {
        if (t < o) sh[t] += sh[t + o];
        __syncthreads();
    }
    float sum = sh[0];
    g_P[b * D + t] = e / sum;
    if (t == 0) g_S[b] = 1.0f / (1.0f + expf(-sign_logits[b]));
}

// ---------------- cp.async helpers ----------------
__device__ __forceinline__ void cp_async16(void* smem_dst, const void* gmem_src) {
    unsigned int saddr = (unsigned int)__cvta_generic_to_shared(smem_dst);
    asm volatile("cp.async.cg.shared.global [%0], [%1], 16;" :: "r"(saddr), "l"(gmem_src));
}
__device__ __forceinline__ void cp_async_commit() { asm volatile("cp.async.commit_group;"); }
__device__ __forceinline__ void cp_async_wait0()  { asm volatile("cp.async.wait_group 0;"); }

// dynamic smem: stage doubled copies: float2[2][HALF][512] = 64 KB
#define SM_DYN_TOTAL (2 * HALF * 512 * 8)

// ---------------- kernel 2: R12 protocol + ALU-free conv addressing ----------------
// 128 CTAs = (lv, ck, sh). 320 threads = 8 conv warps + control (8) + stager (9).
// IDENTICAL synchronization to the passing R12 kernel. Only change: stage holds
// doubled copies (stage[m] = U[m mod 256]) so the conv uses a descending pointer
// with constant offsets — operand values and fmaf order bit-identical.
__global__ void __launch_bounds__(320, 1) scan_sys5b_k(float* __restrict__ out) {
    extern __shared__ float2 stage[];          // [2][HALF][512], 64 KB dynamic

    __shared__ float Ps[A][D];                 // 4 KB
    __shared__ float Ss[A];
    __shared__ float2 scr_s[4][HALF][32];      // 8 KB (quad)
    __shared__ int cdone[HALF];
    __shared__ int scr_free;                   // batches consumed by control
    __shared__ int stage_rdy;                  // batches staged

    const int bid = blockIdx.x;
    const int sh = bid & 1;
    const int ck = (bid >> 1) & 7;
    const int lv = bid >> 4;
    const int tid = threadIdx.x;
    const int lane = tid & 31;
    const int wid = tid >> 5;           // 0..9
    const int j = ck * 32 + lane;
    const int p = lv + 1;
    const float pf = (float)p;

    // indexing helper for the doubled stage: stage[(buf*HALF + k)*512 + m]
    #define STG(buf, k, m) stage[(((buf) * HALF + (k)) << 9) + (m)]

    for (int q = tid; q < A * D; q += 320)
        ((float*)Ps)[q] = g_P[(p - 1) * A * D + q];
    if (tid < A) Ss[tid] = g_S[(p - 1) * A + tid];
    if (tid < HALF) cdone[tid] = 0;
    if (tid == 0) { scr_free = 0; stage_rdy = 0; }
    __syncthreads();

    // ---- prologue: stage batches 0 and 1 (whole CTA), doubled copies ----
    if (lv > 0) {
        for (int w = 0; w < 2; ++w) {
            if (tid == 0) {
                while (vload(&g_prod[lv - 1]) < 8 * (w + 1)) __nanosleep(128);
                __threadfence();
            }
            __syncthreads();
            const int base = w * SB + sh * HALF - 1;
            for (int idx = tid; idx < HALF * 128; idx += 320) {
                int k = idx >> 7, m = idx & 127;
                int slot = (base + k) & (NSLOT - 1);
                const char* src = (const char*)&g_ring[lv - 1][slot][0] + m * 16;
                cp_async16((char*)&STG(w, k, 0)   + m * 16, src);
                cp_async16((char*)&STG(w, k, 256) + m * 16, src);
            }
            cp_async_commit();
        }
        cp_async_wait0();
        __syncthreads();
        if (tid == 0) { __threadfence(); atomicAdd(&g_cons[lv - 1], 2); }
    }
    if (tid == 0) *(volatile int*)&stage_rdy = (lv == 0) ? (NBATCH + 4) : 2;
    __syncthreads();   // LAST full barrier

    if (wid < 8) {
        // ================= CONV WARP (step kk = sh*8 + wid) =================
        const int g = wid;
        const int kk = sh * HALF + g;
        for (int b = 0; b < NBATCH; ++b) {
            while (vload(&stage_rdy) < b + 1) __nanosleep(32);
            while (vload(&scr_free) < b - 3) __nanosleep(32);
            __threadfence_block();

            const int c = (int)__ldg(&g_seq8[b * SB + kk]);
            float ap, am;
            if (p == 1) {
                ap = Ps[c][j];
                am = 0.0f;
            } else {
                const float* __restrict__ row = &Ps[c][0];
                // doubled buffer: STG(b&1, g, m) = U[m mod 256]; descending pointer,
                // operand values and fmaf order bit-identical to the R6 kernel.
                const float2* __restrict__ qp = &STG(b & 1, g, j + 256);
                ap = 0.0f; am = 0.0f;
#pragma unroll 4
                for (int s4 = 0; s4 < D; s4 += 4) {
                    float4 pv = *(const float4*)(row + s4);
                    const float2* u = qp - s4;
                    float2 u0 = u[0], u1 = u[-1], u2 = u[-2], u3 = u[-3];
                    ap = fmaf(u0.x, pv.x, ap); am = fmaf(u0.y, pv.x, am);
                    ap = fmaf(u1.x, pv.y, ap); am = fmaf(u1.y, pv.y, am);
                    ap = fmaf(u2.x, pv.z, ap); am = fmaf(u2.y, pv.z, am);
                    ap = fmaf(u3.x, pv.w, ap); am = fmaf(u3.y, pv.w, am);
                }
            }
            scr_s[b & 3][g][lane] = make_float2(ap, am);
            __threadfence_block();
            if (lane == 0) *(volatile int*)&cdone[g] = b + 1;
        }
    } else if (wid == 8) {
        // ================= CONTROL WARP =================
        float tp = 0.0f, tm = 0.0f;
        for (int b = 0; b < NBATCH; ++b) {
            // all conv warps done with batch b (parallel poll: lane k watches cdone[k])
            if (lane < HALF) { while (vload(&cdone[lane]) < b + 1) __nanosleep(32); }
            __syncwarp();

            if (sh == 1) {
                // ---- shipper ----
                if (lane == 0) { while (vload(&g_scrc[lv][ck]) < b - 3) __nanosleep(64); }
                __syncwarp();
                __threadfence_block();
                float2 v[HALF];
#pragma unroll
                for (int k = 0; k < HALF; ++k) v[k] = scr_s[b & 3][k][lane];
                // release data-depends on every lane's loads (ballot)
                int dep = 0;
#pragma unroll
                for (int k = 0; k < HALF; ++k)
                    dep |= __float_as_int(v[k].x) | __float_as_int(v[k].y);
                unsigned ball = __ballot_sync(0xFFFFFFFFu, dep != 0x7FC00000);
                if (lane == 0) *(volatile int*)&scr_free = (b + 1) | (int)(ball & 0u);
#pragma unroll
                for (int k = 0; k < HALF; ++k)
                    g_scr[lv][ck][b & 3][k][lane] = v[k];
                __threadfence();
                if (lane == 0) *(volatile int*)&g_scrf[lv][ck] = b + 1;
            } else {
                // ---- updater ----
                if (lane == 0) {
                    while (vload(&g_scrf[lv][ck]) < b + 1) __nanosleep(64);
                    // ring gate (R12-proven): writing batch b requires batch (b-15) staged
                    if (lv < 7) while (vload(&g_cons[lv]) < 16 * (b - 14)) __nanosleep(64);
                }
                __syncwarp();
                __threadfence();

                float2 ss[HALF], rr[HALF];
#pragma unroll
                for (int k = 0; k < HALF; ++k) ss[k] = scr_s[b & 3][k][lane];
#pragma unroll
                for (int k = 0; k < HALF; ++k) rr[k] = __ldcg(&g_scr[lv][ck][b & 3][k][lane]);

                // race-free release: flag value data-depends on ALL lanes' loads
                int dep = 0;
#pragma unroll
                for (int k = 0; k < HALF; ++k)
                    dep |= __float_as_int(rr[k].x) | __float_as_int(rr[k].y) |
                           __float_as_int(ss[k].x) | __float_as_int(ss[k].y);
                unsigned ball = __ballot_sync(0xFFFFFFFFu, dep != 0x7FC00000);
                int zero = (int)(ball & 0u);         // always 0, depends on every lane
                if (lane == 0) {
                    *(volatile int*)&scr_free = (b + 1) | zero;
                    *(volatile int*)&g_scrc[lv][ck] = (b + 1) | zero;
                }

                // ---- 16 serial updates (VERBATIM expressions) ----
                __align__(16) unsigned char cb[SB];
                *(int4*)&cb[0] = __ldg((const int4*)&g_seq8[b * SB]);
#pragma unroll
                for (int k = 0; k < SB; ++k) {
                    float2 aa = (k < HALF) ? ss[k] : rr[k - HALF];
                    int cc = (int)cb[k];
                    float fi = (float)(b * SB + k + 1);
                    float z = (pf <= fi) ? (pf / fi) : 0.0f;
                    float sg = Ss[cc];
                    float up = sg * aa.x + (1.0f - sg) * aa.y;
                    float um = sg * aa.y + (1.0f - sg) * aa.x;
                    tp = (1.0f - z) * tp + z * up;
                    tm = (1.0f - z) * tm + z * um;
                    if (lv < 7)
                        g_ring[lv][(b * SB + k) & (NSLOT - 1)][j] = make_float2(tp, tm);
                }
                if (lv < 7) {
                    __threadfence();
                    if (lane == 0) atomicAdd(&g_prod[lv], 1);
                }
            }
            __syncwarp();
        }
        if (lv == 7 && sh == 0) out[j] = tp - tm;
    } else {
        // ================= STAGER WARP (lv > 0 only) =================
        if (lv > 0) {
            for (int w = 2; w < NBATCH; ++w) {
                // stage[w&1] free once conv finished batch w-2
                if (lane < HALF) { while (vload(&cdone[lane]) < w - 1) __nanosleep(64); }
                if (lane == 0) {
                    while (vload(&g_prod[lv - 1]) < 8 * (w + 1)) __nanosleep(64);
                    __threadfence();
                }
                __syncwarp();
                const int base = w * SB + sh * HALF - 1;
                for (int idx = lane; idx < HALF * 128; idx += 32) {
                    int k = idx >> 7, m = idx & 127;
                    int slot = (base + k) & (NSLOT - 1);
                    const char* src = (const char*)&g_ring[lv - 1][slot][0] + m * 16;
                    cp_async16((char*)&STG(w & 1, k, 0)   + m * 16, src);
                    cp_async16((char*)&STG(w & 1, k, 256) + m * 16, src);
                }
                cp_async_commit();
                cp_async_wait0();
                __threadfence_block();
                if (lane == 0) {
                    __threadfence();
                    atomicAdd(&g_cons[lv - 1], 1);
                    *(volatile int*)&stage_rdy = w + 1;
                }
                __syncwarp();
            }
        }
    }
    #undef STG
}

// ---------------- launch ----------------
extern "C" void kernel_launch(void* const* d_in, const int* in_sizes, int n_in,
                              void* d_out, int out_size) {
    const int* seq = nullptr;
    const float* hash_emb = nullptr;
    const float* sign_logits = nullptr;
    for (int i = 0; i < n_in; ++i) {
        if (in_sizes[i] == SEQ)            seq = (const int*)d_in[i];
        else if (in_sizes[i] == L * A * D) hash_emb = (const float*)d_in[i];
        else if (in_sizes[i] == L * A)     sign_logits = (const float*)d_in[i];
    }
    if (!seq)         seq = (const int*)d_in[0];
    if (!hash_emb)    hash_emb = (const float*)d_in[1];
    if (!sign_logits) sign_logits = (const float*)d_in[2];

    float* out = (float*)d_out;

    // host-side attribute set; idempotent, safe on every call
    cudaFuncSetAttribute(scan_sys5b_k, cudaFuncAttributeMaxDynamicSharedMemorySize,
                         SM_DYN_TOTAL);

    pack_seq_k<<<SEQ / 256, 256>>>(seq);
    init_flags_k<<<4, 256>>>();
    precompute_lit_k<<<L * A, D>>>(hash_emb, sign_logits);
    scan_sys5b_k<<<L * 8 * 2, 320, SM_DYN_TOTAL>>>(out);
}

// round 17
// speedup vs baseline: 1.0837x; 1.0837x over previous
#include <cuda_runtime.h>

#define L 8
#define A 4
#define D 256
#define SEQ 16384
#define SB 16
#define HALF 8
#define NBATCH (SEQ / SB)   // 1024
#define NSLOT 256           // ring steps = 16 batches of elasticity
#define SDEPTH 4            // stage buffer depth (batches)

// ---------------- device scratch ----------------
__device__ float g_P[L * A * D];
__device__ float g_S[L * A];
__device__ unsigned char g_seq8[SEQ];
__device__ float2 g_ring[L][NSLOT][D];          // 4 MB level-state ring
__device__ float2 g_scr[L][8][4][HALF][32];     // shipped conv results (quad buf)
__device__ int g_prod[L];                       // +8 per published batch
__device__ int g_cons[L];                       // +16 per staged batch
__device__ int g_scrf[L][8];                    // shipper -> updater
__device__ int g_scrc[L][8];                    // updater -> shipper

__device__ __forceinline__ int vload(const int* p)  { return *(volatile const int*)p; }

// ---------------- kernel 0: pack sequence (verbatim) ----------------
__global__ void pack_seq_k(const int* __restrict__ seq) {
    int i = blockIdx.x * blockDim.x + threadIdx.x;
    if (i < SEQ) g_seq8[i] = (unsigned char)(seq[i] & 3);
}

// ---------------- kernel 0b: reset counters + zero step(-1) ring slot ----------------
__global__ void init_flags_k() {
    int t = blockIdx.x * blockDim.x + threadIdx.x;
    if (t < L) { g_prod[t] = 0; g_cons[t] = 0; }
    if (t < L * 8) { ((int*)g_scrf)[t] = 0; ((int*)g_scrc)[t] = 0; }
    for (int q = t; q < L * D; q += gridDim.x * blockDim.x) {
        int lv = q >> 8, j = q & 255;
        g_ring[lv][NSLOT - 1][j] = make_float2(0.f, 0.f);
    }
}

// ---------------- kernel 1: literal softmax + sigmoid (verbatim) ----------------
__global__ void precompute_lit_k(const float* __restrict__ hash_emb,
                                 const float* __restrict__ sign_logits) {
    int b = blockIdx.x;
    int t = threadIdx.x;
    __shared__ float sh[D];

    float x = hash_emb[b * D + t];
    sh[t] = x;
    __syncthreads();
    for (int o = 128; o > 0; o >>= 1) {
        if (t < o) sh[t] = fmaxf(sh[t], sh[t + o]);
        __syncthreads();
    }
    float mx = sh[0];
    __syncthreads();
    float e = expf(x - mx);
    sh[t] = e;
    __syncthreads();
    for (int o = 128; o > 0; o >>= 1) {
        if (t < o) sh[t] += sh[t + o];
        __syncthreads();
    }
    float sum = sh[0];
    g_P[b * D + t] = e / sum;
    if (t == 0) g_S[b] = 1.0f / (1.0f + expf(-sign_logits[b]));
}

// ---------------- cp.async helpers ----------------
__device__ __forceinline__ void cp_async16(void* smem_dst, const void* gmem_src) {
    unsigned int saddr = (unsigned int)__cvta_generic_to_shared(smem_dst);
    asm volatile("cp.async.cg.shared.global [%0], [%1], 16;" :: "r"(saddr), "l"(gmem_src));
}
__device__ __forceinline__ void cp_async_commit() { asm volatile("cp.async.commit_group;"); }
__device__ __forceinline__ void cp_async_wait0()  { asm volatile("cp.async.wait_group 0;"); }

// dynamic smem: stage doubled copies: float2[SDEPTH][HALF][512] = 128 KB
#define SM_DYN_TOTAL (SDEPTH * HALF * 512 * 8)

// ---------------- kernel 2: race-free releases + depth-4 stage + ALU-free conv ----------------
// 128 CTAs = (lv, ck, sh). 320 threads = 8 conv warps + control (8) + stager (9).
// ALL producer->consumer handoffs use the documented idiom:
//   data ops -> __syncwarp() (cross-lane ordering) -> fence (publish) -> flag store.
// No compiler-foldable pseudo-dependences anywhere.
__global__ void __launch_bounds__(320, 1) scan_sys5d_k(float* __restrict__ out) {
    extern __shared__ float2 stage[];          // [SDEPTH][HALF][512], 128 KB dynamic

    __shared__ float Ps[A][D];                 // 4 KB
    __shared__ float Ss[A];
    __shared__ float2 scr_s[4][HALF][32];      // 8 KB (quad)
    __shared__ int cdone[HALF];
    __shared__ int scr_free;                   // batches consumed by control
    __shared__ int stage_rdy;                  // batches staged

    const int bid = blockIdx.x;
    const int sh = bid & 1;
    const int ck = (bid >> 1) & 7;
    const int lv = bid >> 4;
    const int tid = threadIdx.x;
    const int lane = tid & 31;
    const int wid = tid >> 5;           // 0..9
    const int j = ck * 32 + lane;
    const int p = lv + 1;
    const float pf = (float)p;

    #define STG(buf, k, m) stage[(((buf) * HALF + (k)) << 9) + (m)]

    for (int q = tid; q < A * D; q += 320)
        ((float*)Ps)[q] = g_P[(p - 1) * A * D + q];
    if (tid < A) Ss[tid] = g_S[(p - 1) * A + tid];
    if (tid < HALF) cdone[tid] = 0;
    if (tid == 0) { scr_free = 0; stage_rdy = 0; }
    __syncthreads();

    // ---- prologue: stage batches 0 and 1 (whole CTA), doubled copies ----
    if (lv > 0) {
        for (int w = 0; w < 2; ++w) {
            if (tid == 0) {
                while (vload(&g_prod[lv - 1]) < 8 * (w + 1)) __nanosleep(128);
                __threadfence();
            }
            __syncthreads();
            const int base = w * SB + sh * HALF - 1;
            for (int idx = tid; idx < HALF * 128; idx += 320) {
                int k = idx >> 7, m = idx & 127;
                int slot = (base + k) & (NSLOT - 1);
                const char* src = (const char*)&g_ring[lv - 1][slot][0] + m * 16;
                cp_async16((char*)&STG(w, k, 0)   + m * 16, src);
                cp_async16((char*)&STG(w, k, 256) + m * 16, src);
            }
            cp_async_commit();
        }
        cp_async_wait0();
        __syncthreads();
        if (tid == 0) { __threadfence(); atomicAdd(&g_cons[lv - 1], 2); }
    }
    if (tid == 0) *(volatile int*)&stage_rdy = (lv == 0) ? (NBATCH + 4) : 2;
    __syncthreads();   // LAST full barrier

    if (wid < 8) {
        // ================= CONV WARP (step kk = sh*8 + wid) =================
        const int g = wid;
        const int kk = sh * HALF + g;
        for (int b = 0; b < NBATCH; ++b) {
            while (vload(&stage_rdy) < b + 1) {}      // smem tight-spin
            while (vload(&scr_free) < b - 3) {}       // smem tight-spin
            __threadfence_block();                    // acquire: flag before data reads

            const int c = (int)__ldg(&g_seq8[b * SB + kk]);
            float ap, am;
            if (p == 1) {
                ap = Ps[c][j];
                am = 0.0f;
            } else {
                const float* __restrict__ row = &Ps[c][0];
                const float2* __restrict__ qp = &STG(b & (SDEPTH - 1), g, j + 256);
                ap = 0.0f; am = 0.0f;
#pragma unroll 4
                for (int s4 = 0; s4 < D; s4 += 4) {
                    float4 pv = *(const float4*)(row + s4);
                    const float2* u = qp - s4;
                    float2 u0 = u[0], u1 = u[-1], u2 = u[-2], u3 = u[-3];
                    ap = fmaf(u0.x, pv.x, ap); am = fmaf(u0.y, pv.x, am);
                    ap = fmaf(u1.x, pv.y, ap); am = fmaf(u1.y, pv.y, am);
                    ap = fmaf(u2.x, pv.z, ap); am = fmaf(u2.y, pv.z, am);
                    ap = fmaf(u3.x, pv.w, ap); am = fmaf(u3.y, pv.w, am);
                }
            }
            scr_s[b & 3][g][lane] = make_float2(ap, am);
            __syncwarp();                 // cross-lane: all 32 stores ordered
            __threadfence_block();        // publish before flag
            if (lane == 0) *(volatile int*)&cdone[g] = b + 1;
        }
    } else if (wid == 8) {
        // ================= CONTROL WARP =================
        float tp = 0.0f, tm = 0.0f;
        for (int b = 0; b < NBATCH; ++b) {
            if (lane < HALF) { while (vload(&cdone[lane]) < b + 1) {} }
            __syncwarp();
            __threadfence_block();        // acquire: cdone before scr_s reads

            if (sh == 1) {
                // ---- shipper ----
                if (lane == 0) { while (vload(&g_scrc[lv][ck]) < b - 3) __nanosleep(64); }
                __syncwarp();
                __threadfence();          // acquire: remote release before g_scr rewrite
                float2 v[HALF];
#pragma unroll
                for (int k = 0; k < HALF; ++k) v[k] = scr_s[b & 3][k][lane];
                __syncwarp();             // cross-lane: all loads done
                __threadfence_block();    // order loads before release store
                if (lane == 0) *(volatile int*)&scr_free = b + 1;
#pragma unroll
                for (int k = 0; k < HALF; ++k)
                    g_scr[lv][ck][b & 3][k][lane] = v[k];
                __syncwarp();
                __threadfence();          // publish g_scr before flag
                if (lane == 0) *(volatile int*)&g_scrf[lv][ck] = b + 1;
            } else {
                // ---- updater ----
                if (lane == 0) {
                    while (vload(&g_scrf[lv][ck]) < b + 1) __nanosleep(64);
                    // ring gate (R12-proven): writing batch b requires batch (b-15) staged
                    if (lv < 7) while (vload(&g_cons[lv]) < 16 * (b - 14)) __nanosleep(64);
                }
                __syncwarp();
                __threadfence();          // acquire: flags before data reads

                float2 ss[HALF], rr[HALF];
#pragma unroll
                for (int k = 0; k < HALF; ++k) ss[k] = scr_s[b & 3][k][lane];
#pragma unroll
                for (int k = 0; k < HALF; ++k) rr[k] = __ldcg(&g_scr[lv][ck][b & 3][k][lane]);

                __syncwarp();             // cross-lane: all 32 lanes' loads done
                __threadfence();          // order loads before the release stores
                if (lane == 0) {
                    *(volatile int*)&scr_free = b + 1;
                    *(volatile int*)&g_scrc[lv][ck] = b + 1;
                }

                // ---- 16 serial updates (VERBATIM expressions) ----
                __align__(16) unsigned char cb[SB];
                *(int4*)&cb[0] = __ldg((const int4*)&g_seq8[b * SB]);
#pragma unroll
                for (int k = 0; k < SB; ++k) {
                    float2 aa = (k < HALF) ? ss[k] : rr[k - HALF];
                    int cc = (int)cb[k];
                    float fi = (float)(b * SB + k + 1);
                    float z = (pf <= fi) ? (pf / fi) : 0.0f;
                    float sg = Ss[cc];
                    float up = sg * aa.x + (1.0f - sg) * aa.y;
                    float um = sg * aa.y + (1.0f - sg) * aa.x;
                    tp = (1.0f - z) * tp + z * up;
                    tm = (1.0f - z) * tm + z * um;
                    if (lv < 7)
                        g_ring[lv][(b * SB + k) & (NSLOT - 1)][j] = make_float2(tp, tm);
                }
                if (lv < 7) {
                    __syncwarp();
                    __threadfence();      // publish ring before counter
                    if (lane == 0) atomicAdd(&g_prod[lv], 1);
                }
            }
            __syncwarp();
        }
        if (lv == 7 && sh == 0) out[j] = tp - tm;
    } else {
        // ================= STAGER WARP (lv > 0 only) =================
        if (lv > 0) {
            for (int w = 2; w < NBATCH; ++w) {
                // stage buffer w&3 free once conv finished batch w-4 -> gate w-3
                if (lane < HALF) { while (vload(&cdone[lane]) < w - 3) {} }
                if (lane == 0) {
                    while (vload(&g_prod[lv - 1]) < 8 * (w + 1)) __nanosleep(64);
                }
                __syncwarp();
                __threadfence();          // acquire: producer flag before ring reads
                const int base = w * SB + sh * HALF - 1;
                for (int idx = lane; idx < HALF * 128; idx += 32) {
                    int k = idx >> 7, m = idx & 127;
                    int slot = (base + k) & (NSLOT - 1);
                    const char* src = (const char*)&g_ring[lv - 1][slot][0] + m * 16;
                    cp_async16((char*)&STG(w & (SDEPTH - 1), k, 0)   + m * 16, src);
                    cp_async16((char*)&STG(w & (SDEPTH - 1), k, 256) + m * 16, src);
                }
                cp_async_commit();
                cp_async_wait0();
                __syncwarp();             // cross-lane: every lane's cp.async landed
                __threadfence_block();    // publish smem before flag
                if (lane == 0) {
                    __threadfence();
                    atomicAdd(&g_cons[lv - 1], 1);
                    *(volatile int*)&stage_rdy = w + 1;
                }
                __syncwarp();
            }
        }
    }
    #undef STG
}

// ---------------- launch ----------------
extern "C" void kernel_launch(void* const* d_in, const int* in_sizes, int n_in,
                              void* d_out, int out_size) {
    const int* seq = nullptr;
    const float* hash_emb = nullptr;
    const float* sign_logits = nullptr;
    for (int i = 0; i < n_in; ++i) {
        if (in_sizes[i] == SEQ)            seq = (const int*)d_in[i];
        else if (in_sizes[i] == L * A * D) hash_emb = (const float*)d_in[i];
        else if (in_sizes[i] == L * A)     sign_logits = (const float*)d_in[i];
    }
    if (!seq)         seq = (const int*)d_in[0];
    if (!hash_emb)    hash_emb = (const float*)d_in[1];
    if (!sign_logits) sign_logits = (const float*)d_in[2];

    float* out = (float*)d_out;

    cudaFuncSetAttribute(scan_sys5d_k, cudaFuncAttributeMaxDynamicSharedMemorySize,
                         SM_DYN_TOTAL);

    pack_seq_k<<<SEQ / 256, 256>>>(seq);
    init_flags_k<<<4, 256>>>();
    precompute_lit_k<<<L * A, D>>>(hash_emb, sign_logits);
    scan_sys5d_k<<<L * 8 * 2, 320, SM_DYN_TOTAL>>>(out);
}